// round 15
// baseline (speedup 1.0000x reference)
#include <cuda_runtime.h>
#include <cuda_fp16.h>
#include <math.h>
#include <stdint.h>

#define TOKENS 4096
#define EMB    768
#define NLAYER 12
#define NHEAD  12
#define HDIM   64
#define SEQ    1024
#define NBATCH 4
#define VOCAB  50257
#define FFDIM  3072
#define QKVDIM 2304

// -------------------- scratch (static device globals; no allocation) --------
__device__ float  g_x  [TOKENS * EMB];
__device__ __half g_ah [TOKENS * EMB];
__device__ __half g_qkvh[TOKENS * QKVDIM];
__device__ __half g_yh [TOKENS * EMB];
__device__ __half g_mh [TOKENS * FFDIM];
__device__ __half g_qkvH[(size_t)NLAYER * QKVDIM * EMB];
__device__ __half g_atpH[(size_t)NLAYER * EMB * EMB];
__device__ __half g_fcH [(size_t)NLAYER * FFDIM * EMB];
__device__ __half g_fcL [(size_t)NLAYER * FFDIM * EMB];
__device__ __half g_fpH [(size_t)NLAYER * EMB * FFDIM];
__device__ __half g_lmH [(size_t)VOCAB * EMB];

// ------------------------------------------------------------- helpers
__device__ __forceinline__ float gelu_f(float x) {
    float x3 = x * x * x;
    return 0.5f * x * (1.f + tanhf(0.7978845608028654f * (x + 0.044715f * x3)));
}
__device__ __forceinline__ uint32_t pack_f16(float x0, float x1) {
    uint32_t u;
    asm("{.reg .b16 l,h; cvt.rn.f16.f32 l,%1; cvt.rn.f16.f32 h,%2; mov.b32 %0,{l,h};}"
        : "=r"(u) : "f"(x0), "f"(x1));
    return u;
}
__device__ __forceinline__ void mma_f16(float* c, const uint32_t* a, const uint32_t* b) {
    asm volatile(
        "mma.sync.aligned.m16n8k16.row.col.f32.f16.f16.f32 "
        "{%0,%1,%2,%3}, {%4,%5,%6,%7}, {%8,%9}, {%0,%1,%2,%3};"
        : "+f"(c[0]), "+f"(c[1]), "+f"(c[2]), "+f"(c[3])
        : "r"(a[0]), "r"(a[1]), "r"(a[2]), "r"(a[3]), "r"(b[0]), "r"(b[1]));
}
__device__ __forceinline__ void ldmx4(uint32_t& r0, uint32_t& r1,
                                      uint32_t& r2, uint32_t& r3, uint32_t addr) {
    asm volatile("ldmatrix.sync.aligned.m8n8.x4.shared.b16 {%0,%1,%2,%3}, [%4];"
                 : "=r"(r0), "=r"(r1), "=r"(r2), "=r"(r3) : "r"(addr));
}
__device__ __forceinline__ void ldmx2(uint32_t& r0, uint32_t& r1, uint32_t addr) {
    asm volatile("ldmatrix.sync.aligned.m8n8.x2.shared.b16 {%0,%1}, [%2];"
                 : "=r"(r0), "=r"(r1) : "r"(addr));
}
__device__ __forceinline__ void ldmx4t(uint32_t& r0, uint32_t& r1,
                                       uint32_t& r2, uint32_t& r3, uint32_t addr) {
    asm volatile("ldmatrix.sync.aligned.m8n8.x4.trans.shared.b16 {%0,%1,%2,%3}, [%4];"
                 : "=r"(r0), "=r"(r1), "=r"(r2), "=r"(r3) : "r"(addr));
}
__device__ __forceinline__ void cpa16(uint32_t dst, const void* src, int srcsz) {
    asm volatile("cp.async.ca.shared.global [%0], [%1], 16, %2;"
                 :: "r"(dst), "l"(src), "r"(srcsz) : "memory");
}
#define CP_COMMIT() asm volatile("cp.async.commit_group;" ::: "memory")
#define CP_WAIT0()  asm volatile("cp.async.wait_group 0;" ::: "memory")
#define CP_WAIT1()  asm volatile("cp.async.wait_group 1;" ::: "memory")

// ---------------------------------------------------------------- embedding
__global__ void embed_kernel(const int* __restrict__ tok,
                             const float* __restrict__ wte,
                             const float* __restrict__ wpe,
                             float* __restrict__ x) {
    int idx = blockIdx.x * blockDim.x + threadIdx.x;
    if (idx >= TOKENS * EMB) return;
    int t = idx / EMB;
    int e = idx - t * EMB;
    x[idx] = wte[(size_t)tok[t] * EMB + e] + wpe[e];
}

// --------------------------------- layernorm (warp-per-row, fp16 output)
__global__ void ln_kernel(const float* __restrict__ x,
                          const float* __restrict__ w,
                          const float* __restrict__ bb,
                          __half* __restrict__ o) {
    const int row  = blockIdx.x * 8 + (threadIdx.x >> 5);
    const int lane = threadIdx.x & 31;
    const float* xr = x + (size_t)row * EMB;

    float4 v[6];
    float s = 0.f, sq = 0.f;
    #pragma unroll
    for (int i = 0; i < 6; i++) {
        v[i] = *(const float4*)(xr + lane * 4 + i * 128);
        s  += v[i].x + v[i].y + v[i].z + v[i].w;
        sq += v[i].x * v[i].x + v[i].y * v[i].y
            + v[i].z * v[i].z + v[i].w * v[i].w;
    }
    #pragma unroll
    for (int off = 16; off; off >>= 1) {
        s  += __shfl_xor_sync(0xffffffffu, s, off);
        sq += __shfl_xor_sync(0xffffffffu, sq, off);
    }
    const float mean = s * (1.f / EMB);
    const float rstd = rsqrtf(sq * (1.f / EMB) - mean * mean + 1e-5f);

    __half* orow = o + (size_t)row * EMB;
    #pragma unroll
    for (int i = 0; i < 6; i++) {
        const int c = lane * 4 + i * 128;
        float4 wv = *(const float4*)(w + c);
        float4 bv = *(const float4*)(bb + c);
        float r0 = (v[i].x - mean) * rstd * wv.x + bv.x;
        float r1 = (v[i].y - mean) * rstd * wv.y + bv.y;
        float r2 = (v[i].z - mean) * rstd * wv.z + bv.z;
        float r3 = (v[i].w - mean) * rstd * wv.w + bv.w;
        *(uint2*)(orow + c) = make_uint2(pack_f16(r0, r1), pack_f16(r2, r3));
    }
}

// --------------------------------------------- transpose + fp16 hi/lo split
__global__ void transpose_split_kernel(const float* __restrict__ in,
                                       __half* __restrict__ oh,
                                       __half* __restrict__ ol,
                                       int K, int N) {
    __shared__ float t[32][33];
    const size_t off = (size_t)blockIdx.z * K * N;
    int n0 = blockIdx.x * 32, k0 = blockIdx.y * 32;
    int x = threadIdx.x, y = threadIdx.y;
    #pragma unroll
    for (int i = 0; i < 32; i += 8)
        t[y + i][x] = in[off + (size_t)(k0 + y + i) * N + n0 + x];
    __syncthreads();
    #pragma unroll
    for (int i = 0; i < 32; i += 8) {
        float v = t[x][y + i];
        __half h = __float2half_rn(v);
        __half l = __float2half_rn(v - __half2float(h));
        size_t o = off + (size_t)(n0 + y + i) * K + k0 + x;
        oh[o] = h; ol[o] = l;
    }
}

// ------------------------------------------ transpose + fp16 (hi only)
__global__ void transpose_cvt_kernel(const float* __restrict__ in,
                                     __half* __restrict__ oh,
                                     int K, int N) {
    __shared__ float t[32][33];
    const size_t off = (size_t)blockIdx.z * K * N;
    int n0 = blockIdx.x * 32, k0 = blockIdx.y * 32;
    int x = threadIdx.x, y = threadIdx.y;
    #pragma unroll
    for (int i = 0; i < 32; i += 8)
        t[y + i][x] = in[off + (size_t)(k0 + y + i) * N + n0 + x];
    __syncthreads();
    #pragma unroll
    for (int i = 0; i < 32; i += 8)
        oh[off + (size_t)(n0 + y + i) * K + k0 + x] = __float2half_rn(t[x][y + i]);
}

// ---------------------------------------------- elementwise fp16 convert
__global__ void cvt_kernel(const float* __restrict__ in,
                           __half* __restrict__ oh, int n) {
    int i = blockIdx.x * blockDim.x + threadIdx.x;
    if (i >= n) return;
    oh[i] = __float2half_rn(in[i]);
}

// ------------------------------------------- fp16 mma.sync GEMM (k64 chunks)
// C[M,N] = A[M,K] @ B[N,K]^T.  A fp16 (producer-rounded).
// SPLIT: B = Bh + Bl (2-stage pipe) vs Bh only (3-stage pipe).
// EPI 0: +bias -> half | EPI 1: +bias+res(fp32) -> float
// EPI 2: +bias+gelu -> half | EPI 4: plain, N-guard -> float (M-major raster)
#define BP 72
template <int EPI, int NT, bool SPLIT>
__global__ void __launch_bounds__(256, 2)
gemm_f16(const __half* __restrict__ Ah,
         const __half* __restrict__ Bh, const __half* __restrict__ Bl,
         const float* __restrict__ bias, const float* __restrict__ res,
         void* __restrict__ Cv, int M, int N, int K) {
    constexpr int STG  = SPLIT ? 2 : 3;
    constexpr int ABUF = 128 * BP;
    constexpr int BBUF = NT * BP;
    constexpr int NBT  = NT / 32;

    extern __shared__ __half sm[];
    __half* sA  = sm;                       // STG x ABUF
    __half* sBh = sm + STG * ABUF;          // STG x BBUF
    __half* sBl = sBh + STG * BBUF;         // STG x BBUF (SPLIT only)
    const uint32_t uA  = (uint32_t)__cvta_generic_to_shared(sA);
    const uint32_t uBh = (uint32_t)__cvta_generic_to_shared(sBh);
    const uint32_t uBl = (uint32_t)__cvta_generic_to_shared(sBl);

    const int tid  = threadIdx.x;
    const int wid  = tid >> 5;
    const int lane = tid & 31;
    const int grp  = lane >> 2;
    const int tig  = lane & 3;
    // EPI 4 (LM head): M-major raster — consecutive CTAs share the B tile.
    const int bm = (EPI == 4 ? blockIdx.x : blockIdx.y) * 128;
    const int bn = (EPI == 4 ? blockIdx.y : blockIdx.x) * NT;
    const int wm0 = (wid & 1) * 64;
    const int wn0 = (wid >> 1) * (NT / 4);

    const int a_row = (lane & 15);
    const int a_k   = (lane >> 4) << 3;
    const int b_row = (lane & 7) + ((lane >> 4) << 3);
    const int b_k   = ((lane >> 3) & 1) << 3;
    const int b2_row = lane & 7;
    const int b2_k   = ((lane >> 3) & 1) << 3;

    float cf[4][NBT][4];
    #pragma unroll
    for (int i = 0; i < 4; i++)
        #pragma unroll
        for (int j = 0; j < NBT; j++)
            #pragma unroll
            for (int r = 0; r < 4; r++) cf[i][j][r] = 0.f;

    const int KC = K >> 6;

    auto stage = [&](int k0, int p) {
        #pragma unroll
        for (int ps = 0; ps < 4; ps++) {
            int s = tid + ps * 256;
            int row = s >> 3;
            int c16 = (s & 7) * 8;
            uint32_t doff = (uint32_t)(p * ABUF + row * BP + c16) * 2;
            cpa16(uA + doff, Ah + (size_t)(bm + row) * K + k0 + c16, 16);
        }
        #pragma unroll
        for (int ps = 0; ps < NT / 32; ps++) {
            int s = tid + ps * 256;
            int row = s >> 3;
            int c16 = (s & 7) * 8;
            int gr = bn + row, sz = 16;
            if (EPI == 4 && gr >= N) { gr = 0; sz = 0; }
            uint32_t doff = (uint32_t)(p * BBUF + row * BP + c16) * 2;
            cpa16(uBh + doff, Bh + (size_t)gr * K + k0 + c16, sz);
            if (SPLIT)
                cpa16(uBl + doff, Bl + (size_t)gr * K + k0 + c16, sz);
        }
        CP_COMMIT();
    };

    #pragma unroll
    for (int s = 0; s < STG - 1; s++) stage(s << 6, s);

    for (int c = 0; c < KC; c++) {
        const int p = c % STG;
        // pipeline drain discipline: with 3 stages, wait_group 1 is only valid
        // while a younger group exists; the tail must fall back to wait_group 0.
        if (STG == 2) { CP_WAIT0(); }
        else          { if (c + 1 < KC) CP_WAIT1(); else CP_WAIT0(); }
        __syncthreads();
        const int nc = c + STG - 1;
        if (nc < KC) stage(nc << 6, nc % STG);

        const uint32_t bufA  = uA  + (uint32_t)(p * ABUF) * 2;
        const uint32_t bufBh = uBh + (uint32_t)(p * BBUF) * 2;
        const uint32_t bufBl = uBl + (uint32_t)(p * BBUF) * 2;
        #pragma unroll
        for (int ks = 0; ks < 4; ks++) {
            const int k0 = ks * 16;
            uint32_t bh[NBT][2], bl[NBT][2];
            uint32_t bo = (uint32_t)((wn0 + b_row) * BP + k0 + b_k) * 2;
            #pragma unroll
            for (int g = 0; g < NBT / 2; g++) {
                ldmx4(bh[2 * g][0], bh[2 * g][1], bh[2 * g + 1][0], bh[2 * g + 1][1],
                      bufBh + bo + (uint32_t)(g * 16 * BP) * 2);
                if (SPLIT)
                    ldmx4(bl[2 * g][0], bl[2 * g][1], bl[2 * g + 1][0], bl[2 * g + 1][1],
                          bufBl + bo + (uint32_t)(g * 16 * BP) * 2);
            }
            if (NBT & 1) {
                uint32_t bo2 = (uint32_t)((wn0 + (NBT - 1) * 8 + b2_row) * BP + k0 + b2_k) * 2;
                ldmx2(bh[NBT - 1][0], bh[NBT - 1][1], bufBh + bo2);
                if (SPLIT)
                    ldmx2(bl[NBT - 1][0], bl[NBT - 1][1], bufBl + bo2);
            }
            #pragma unroll
            for (int mt = 0; mt < 4; mt++) {
                uint32_t a[4];
                uint32_t ao = (uint32_t)((wm0 + mt * 16 + a_row) * BP + k0 + a_k) * 2;
                ldmx4(a[0], a[1], a[2], a[3], bufA + ao);
                #pragma unroll
                for (int nt = 0; nt < NBT; nt++) {
                    mma_f16(cf[mt][nt], a, bh[nt]);
                    if (SPLIT) mma_f16(cf[mt][nt], a, bl[nt]);
                }
            }
        }
    }

    // ---------------- epilogue ----------------
    #pragma unroll
    for (int mt = 0; mt < 4; mt++) {
        #pragma unroll
        for (int half = 0; half < 2; half++) {
            const int row = bm + wm0 + mt * 16 + grp + half * 8;
            #pragma unroll
            for (int nt = 0; nt < NBT; nt++) {
                const int col = bn + wn0 + nt * 8 + 2 * tig;
                float v0 = cf[mt][nt][half * 2 + 0];
                float v1 = cf[mt][nt][half * 2 + 1];
                if (EPI == 4) {
                    float* C = (float*)Cv;
                    if (col < N)     C[(size_t)row * N + col]     = v0;
                    if (col + 1 < N) C[(size_t)row * N + col + 1] = v1;
                } else {
                    v0 += bias[col];
                    v1 += bias[col + 1];
                    if (EPI == 1) {
                        const float* rp = res + (size_t)row * N + col;
                        v0 += rp[0]; v1 += rp[1];
                        *(float2*)((float*)Cv + (size_t)row * N + col) = make_float2(v0, v1);
                    } else {
                        if (EPI == 2) { v0 = gelu_f(v0); v1 = gelu_f(v1); }
                        *(uint32_t*)((__half*)Cv + (size_t)row * N + col) = pack_f16(v0, v1);
                    }
                }
            }
        }
    }
}

// ------------------------------------ fp16 mma.sync flash attention (v4)
// One Q tile per block, largest tiles launched first (work-stealing fills tail).
#define APT 72
#define ATILE (64 * APT)
__global__ void __launch_bounds__(128)
attn_mma(const __half* __restrict__ qkv, __half* __restrict__ y) {
    extern __shared__ __half sh[];
    __half* sQ = sh;
    __half* sK = sh + ATILE;
    __half* sV = sh + 3 * ATILE;
    const uint32_t uQ = (uint32_t)__cvta_generic_to_shared(sQ);
    const uint32_t uK = (uint32_t)__cvta_generic_to_shared(sK);
    const uint32_t uV = (uint32_t)__cvta_generic_to_shared(sV);

    const int NT = SEQ / 64;
    const int tq = NT - 1 - (int)blockIdx.x;   // largest-first
    const int h = blockIdx.y, b = blockIdx.z;
    const int tid  = threadIdx.x;
    const int wid  = tid >> 5;
    const int lane = tid & 31;
    const int grp  = lane >> 2;
    const int tig  = lane & 3;
    const float scale = 0.036084391824351615f;  // 1/sqrt(768)

    const int a_row = lane & 15;
    const int a_k   = (lane >> 4) << 3;
    const int b_row = (lane & 7) + ((lane >> 4) << 3);
    const int b_k   = ((lane >> 3) & 1) << 3;

    auto stageKV = [&](int ks, int p) {
        #pragma unroll
        for (int ps = 0; ps < 4; ps++) {
            int s = tid + ps * 128;
            int row = s >> 3;
            int ch = (s & 7) * 8;
            const __half* base = qkv + ((size_t)b * SEQ + (size_t)ks * 64 + row) * QKVDIM
                               + h * HDIM + ch;
            uint32_t doff = (uint32_t)(p * ATILE + row * APT + ch) * 2;
            cpa16(uK + doff, base + EMB, 16);
            cpa16(uV + doff, base + 2 * EMB, 16);
        }
        CP_COMMIT();
    };

    #pragma unroll
    for (int ps = 0; ps < 4; ps++) {
        int s = tid + ps * 128;
        int row = s >> 3;
        int ch = (s & 7) * 8;
        cpa16(uQ + (uint32_t)(row * APT + ch) * 2,
              qkv + ((size_t)b * SEQ + (size_t)tq * 64 + row) * QKVDIM + h * HDIM + ch, 16);
    }
    CP_COMMIT();
    stageKV(0, 0);
    CP_WAIT0();
    __syncthreads();

    uint32_t qf[4][4];
    #pragma unroll
    for (int kt = 0; kt < 4; kt++) {
        uint32_t ao = (uint32_t)((wid * 16 + a_row) * APT + kt * 16 + a_k) * 2;
        ldmx4(qf[kt][0], qf[kt][1], qf[kt][2], qf[kt][3], uQ + ao);
    }

    float o[8][4];
    #pragma unroll
    for (int nt = 0; nt < 8; nt++)
        #pragma unroll
        for (int r = 0; r < 4; r++) o[nt][r] = 0.f;
    float m0 = -1e30f, m1 = -1e30f, l0 = 0.f, l1 = 0.f;

    const int row_g0 = tq * 64 + wid * 16 + grp;
    const int row_g1 = row_g0 + 8;

    for (int ks = 0; ks <= tq; ks++) {
        const int p = ks & 1;
        if (ks > 0) { CP_WAIT0(); __syncthreads(); }
        if (ks + 1 <= tq) stageKV(ks + 1, 1 - p);

        const uint32_t bufK = uK + (uint32_t)(p * ATILE) * 2;
        const uint32_t bufV = uV + (uint32_t)(p * ATILE) * 2;

        float s[8][4];
        #pragma unroll
        for (int nt = 0; nt < 8; nt++)
            #pragma unroll
            for (int r = 0; r < 4; r++) s[nt][r] = 0.f;
        #pragma unroll
        for (int kt = 0; kt < 4; kt++) {
            #pragma unroll
            for (int ntp = 0; ntp < 4; ntp++) {
                uint32_t kb[2][2];
                uint32_t bo = (uint32_t)((ntp * 16 + b_row) * APT + kt * 16 + b_k) * 2;
                ldmx4(kb[0][0], kb[0][1], kb[1][0], kb[1][1], bufK + bo);
                mma_f16(s[2 * ntp + 0], qf[kt], kb[0]);
                mma_f16(s[2 * ntp + 1], qf[kt], kb[1]);
            }
        }

        const bool diag = (ks == tq);
        #pragma unroll
        for (int nt = 0; nt < 8; nt++) {
            int c = ks * 64 + nt * 8 + 2 * tig;
            #pragma unroll
            for (int r = 0; r < 4; r++) s[nt][r] *= scale;
            if (diag) {
                if (c > row_g0)     s[nt][0] = -1e30f;
                if (c + 1 > row_g0) s[nt][1] = -1e30f;
                if (c > row_g1)     s[nt][2] = -1e30f;
                if (c + 1 > row_g1) s[nt][3] = -1e30f;
            }
        }

        float t0 = -1e30f, t1 = -1e30f;
        #pragma unroll
        for (int nt = 0; nt < 8; nt++) {
            t0 = fmaxf(t0, fmaxf(s[nt][0], s[nt][1]));
            t1 = fmaxf(t1, fmaxf(s[nt][2], s[nt][3]));
        }
        #pragma unroll
        for (int off = 1; off < 4; off <<= 1) {
            t0 = fmaxf(t0, __shfl_xor_sync(0xffffffffu, t0, off));
            t1 = fmaxf(t1, __shfl_xor_sync(0xffffffffu, t1, off));
        }
        float nm0 = fmaxf(m0, t0), nm1 = fmaxf(m1, t1);
        float cr0 = __expf(m0 - nm0), cr1 = __expf(m1 - nm1);
        m0 = nm0; m1 = nm1;
        float rs0 = 0.f, rs1 = 0.f;
        uint32_t p01[8], p23[8];
        #pragma unroll
        for (int nt = 0; nt < 8; nt++) {
            float e0 = __expf(s[nt][0] - nm0);
            float e1 = __expf(s[nt][1] - nm0);
            float e2 = __expf(s[nt][2] - nm1);
            float e3 = __expf(s[nt][3] - nm1);
            rs0 += e0 + e1; rs1 += e2 + e3;
            p01[nt] = pack_f16(e0, e1);
            p23[nt] = pack_f16(e2, e3);
        }
        #pragma unroll
        for (int off = 1; off < 4; off <<= 1) {
            rs0 += __shfl_xor_sync(0xffffffffu, rs0, off);
            rs1 += __shfl_xor_sync(0xffffffffu, rs1, off);
        }
        l0 = l0 * cr0 + rs0;
        l1 = l1 * cr1 + rs1;
        #pragma unroll
        for (int nt = 0; nt < 8; nt++) {
            o[nt][0] *= cr0; o[nt][1] *= cr0;
            o[nt][2] *= cr1; o[nt][3] *= cr1;
        }

        #pragma unroll
        for (int kt = 0; kt < 4; kt++) {
            uint32_t a[4] = { p01[2 * kt], p23[2 * kt], p01[2 * kt + 1], p23[2 * kt + 1] };
            #pragma unroll
            for (int ntp = 0; ntp < 4; ntp++) {
                uint32_t vb[2][2];
                uint32_t vo = (uint32_t)((kt * 16 + a_row) * APT + ntp * 16 + a_k) * 2;
                ldmx4t(vb[0][0], vb[0][1], vb[1][0], vb[1][1], bufV + vo);
                mma_f16(o[2 * ntp + 0], a, vb[0]);
                mma_f16(o[2 * ntp + 1], a, vb[1]);
            }
        }
    }

    float inv0 = 1.f / l0, inv1 = 1.f / l1;
    __half* y0 = y + ((size_t)b * SEQ + (size_t)tq * 64 + wid * 16 + grp) * EMB + h * HDIM;
    __half* y1 = y0 + 8 * EMB;
    #pragma unroll
    for (int nt = 0; nt < 8; nt++) {
        int c = nt * 8 + 2 * tig;
        *(uint32_t*)(y0 + c) = pack_f16(o[nt][0] * inv0, o[nt][1] * inv0);
        *(uint32_t*)(y1 + c) = pack_f16(o[nt][2] * inv1, o[nt][3] * inv1);
    }
}

// -------------------------------------------------------------------- launch
extern "C" void kernel_launch(void* const* d_in, const int* in_sizes, int n_in,
                              void* d_out, int out_size) {
    const int*   tokens = (const int*)  d_in[0];
    const float* wte    = (const float*)d_in[1];
    const float* wpe    = (const float*)d_in[2];
    const float* ln1w   = (const float*)d_in[3];
    const float* ln1b   = (const float*)d_in[4];
    const float* qkvw   = (const float*)d_in[5];
    const float* qkvb   = (const float*)d_in[6];
    const float* atpw   = (const float*)d_in[7];
    const float* atpb   = (const float*)d_in[8];
    const float* ln2w   = (const float*)d_in[9];
    const float* ln2b   = (const float*)d_in[10];
    const float* fcw    = (const float*)d_in[11];
    const float* fcb    = (const float*)d_in[12];
    const float* fpw    = (const float*)d_in[13];
    const float* fpb    = (const float*)d_in[14];
    const float* lnfw   = (const float*)d_in[15];
    const float* lnfb   = (const float*)d_in[16];
    const float* lmw    = (const float*)d_in[17];
    float* out = (float*)d_out;

    float* px;
    __half *pah, *pqkvh, *pyh, *pmh;
    __half *qh, *ah, *fh, *fl, *ph, *lh;
    cudaGetSymbolAddress((void**)&px,    g_x);
    cudaGetSymbolAddress((void**)&pah,   g_ah);
    cudaGetSymbolAddress((void**)&pqkvh, g_qkvh);
    cudaGetSymbolAddress((void**)&pyh,   g_yh);
    cudaGetSymbolAddress((void**)&pmh,   g_mh);
    cudaGetSymbolAddress((void**)&qh, g_qkvH);
    cudaGetSymbolAddress((void**)&ah, g_atpH);
    cudaGetSymbolAddress((void**)&fh, g_fcH);  cudaGetSymbolAddress((void**)&fl, g_fcL);
    cudaGetSymbolAddress((void**)&ph, g_fpH);
    cudaGetSymbolAddress((void**)&lh, g_lmH);

    const int smem128s2 = (2 * 128 * BP + 4 * 128 * BP) * 2;  // 110592 (fc, split, 2-stage)
    const int smem96s1  = (3 * 128 * BP + 3 * 96 * BP) * 2;   // 96768  (proj/fp, 3-stage)
    const int smem128s1 = (3 * 128 * BP + 3 * 128 * BP) * 2;  // 110592 (qkv/lm, 3-stage)
    cudaFuncSetAttribute((gemm_f16<0, 128, false>), cudaFuncAttributeMaxDynamicSharedMemorySize, smem128s1);
    cudaFuncSetAttribute((gemm_f16<2, 128, true>),  cudaFuncAttributeMaxDynamicSharedMemorySize, smem128s2);
    cudaFuncSetAttribute((gemm_f16<1, 96, false>),  cudaFuncAttributeMaxDynamicSharedMemorySize, smem96s1);
    cudaFuncSetAttribute((gemm_f16<4, 128, false>), cudaFuncAttributeMaxDynamicSharedMemorySize, smem128s1);

    const int asmem = 5 * ATILE * sizeof(__half);  // 46080
    cudaFuncSetAttribute(attn_mma, cudaFuncAttributeMaxDynamicSharedMemorySize, asmem);

    dim3 tb(32, 8);
    transpose_cvt_kernel<<<dim3(QKVDIM / 32, EMB / 32, NLAYER), tb>>>(qkvw, qh, EMB, QKVDIM);
    transpose_cvt_kernel<<<dim3(EMB / 32,    EMB / 32, NLAYER), tb>>>(atpw, ah, EMB, EMB);
    transpose_split_kernel<<<dim3(FFDIM / 32,  EMB / 32, NLAYER), tb>>>(fcw,  fh, fl, EMB, FFDIM);
    transpose_cvt_kernel<<<dim3(EMB / 32,  FFDIM / 32, NLAYER), tb>>>(fpw,  ph, FFDIM, EMB);
    cvt_kernel<<<(VOCAB * EMB + 255) / 256, 256>>>(lmw, lh, VOCAB * EMB);

    embed_kernel<<<(TOKENS * EMB + 255) / 256, 256>>>(tokens, wte, wpe, px);

    for (int i = 0; i < NLAYER; i++) {
        ln_kernel<<<TOKENS / 8, 256>>>(px, ln1w + i * EMB, ln1b + i * EMB, pah);

        gemm_f16<0, 128, false><<<dim3(QKVDIM / 128, TOKENS / 128), 256, smem128s1>>>(
            pah, qh + (size_t)i * QKVDIM * EMB, nullptr,
            qkvb + i * QKVDIM, nullptr, pqkvh, TOKENS, QKVDIM, EMB);

        attn_mma<<<dim3(SEQ / 64, NHEAD, NBATCH), 128, asmem>>>(pqkvh, pyh);

        gemm_f16<1, 96, false><<<dim3(EMB / 96, TOKENS / 128), 256, smem96s1>>>(
            pyh, ah + (size_t)i * EMB * EMB, nullptr,
            atpb + i * EMB, px, px, TOKENS, EMB, EMB);

        ln_kernel<<<TOKENS / 8, 256>>>(px, ln2w + i * EMB, ln2b + i * EMB, pah);

        gemm_f16<2, 128, true><<<dim3(FFDIM / 128, TOKENS / 128), 256, smem128s2>>>(
            pah, fh + (size_t)i * FFDIM * EMB, fl + (size_t)i * FFDIM * EMB,
            fcb + i * FFDIM, nullptr, pmh, TOKENS, FFDIM, EMB);

        gemm_f16<1, 96, false><<<dim3(EMB / 96, TOKENS / 128), 256, smem96s1>>>(
            pmh, ph + (size_t)i * EMB * FFDIM, nullptr,
            fpb + i * EMB, px, px, TOKENS, EMB, FFDIM);
    }

    ln_kernel<<<TOKENS / 8, 256>>>(px, lnfw, lnfb, pah);

    gemm_f16<4, 128, false><<<dim3(TOKENS / 128, (VOCAB + 127) / 128), 256, smem128s1>>>(
        pah, lh, nullptr, nullptr, nullptr, out, TOKENS, VOCAB, EMB);
}

// round 16
// speedup vs baseline: 1.0549x; 1.0549x over previous
#include <cuda_runtime.h>
#include <cuda_fp16.h>
#include <math.h>
#include <stdint.h>

#define TOKENS 4096
#define EMB    768
#define NLAYER 12
#define NHEAD  12
#define HDIM   64
#define SEQ    1024
#define NBATCH 4
#define VOCAB  50257
#define FFDIM  3072
#define QKVDIM 2304

// -------------------- scratch (static device globals; no allocation) --------
__device__ float  g_x  [TOKENS * EMB];
__device__ __half g_ah [TOKENS * EMB];
__device__ __half g_qkvh[TOKENS * QKVDIM];
__device__ __half g_yh [TOKENS * EMB];
__device__ __half g_mh [TOKENS * FFDIM];
__device__ __half g_qkvH[(size_t)NLAYER * QKVDIM * EMB];
__device__ __half g_atpH[(size_t)NLAYER * EMB * EMB];
__device__ __half g_fcH [(size_t)NLAYER * FFDIM * EMB];
__device__ __half g_fcL [(size_t)NLAYER * FFDIM * EMB];
__device__ __half g_fpH [(size_t)NLAYER * EMB * FFDIM];
__device__ __half g_lmH [(size_t)VOCAB * EMB];

// ------------------------------------------------------------- helpers
__device__ __forceinline__ float gelu_f(float x) {
    float x3 = x * x * x;
    return 0.5f * x * (1.f + tanhf(0.7978845608028654f * (x + 0.044715f * x3)));
}
__device__ __forceinline__ uint32_t pack_f16(float x0, float x1) {
    uint32_t u;
    asm("{.reg .b16 l,h; cvt.rn.f16.f32 l,%1; cvt.rn.f16.f32 h,%2; mov.b32 %0,{l,h};}"
        : "=r"(u) : "f"(x0), "f"(x1));
    return u;
}
__device__ __forceinline__ void mma_f16(float* c, const uint32_t* a, const uint32_t* b) {
    asm volatile(
        "mma.sync.aligned.m16n8k16.row.col.f32.f16.f16.f32 "
        "{%0,%1,%2,%3}, {%4,%5,%6,%7}, {%8,%9}, {%0,%1,%2,%3};"
        : "+f"(c[0]), "+f"(c[1]), "+f"(c[2]), "+f"(c[3])
        : "r"(a[0]), "r"(a[1]), "r"(a[2]), "r"(a[3]), "r"(b[0]), "r"(b[1]));
}
__device__ __forceinline__ void ldmx4(uint32_t& r0, uint32_t& r1,
                                      uint32_t& r2, uint32_t& r3, uint32_t addr) {
    asm volatile("ldmatrix.sync.aligned.m8n8.x4.shared.b16 {%0,%1,%2,%3}, [%4];"
                 : "=r"(r0), "=r"(r1), "=r"(r2), "=r"(r3) : "r"(addr));
}
__device__ __forceinline__ void ldmx2(uint32_t& r0, uint32_t& r1, uint32_t addr) {
    asm volatile("ldmatrix.sync.aligned.m8n8.x2.shared.b16 {%0,%1}, [%2];"
                 : "=r"(r0), "=r"(r1) : "r"(addr));
}
__device__ __forceinline__ void ldmx4t(uint32_t& r0, uint32_t& r1,
                                       uint32_t& r2, uint32_t& r3, uint32_t addr) {
    asm volatile("ldmatrix.sync.aligned.m8n8.x4.trans.shared.b16 {%0,%1,%2,%3}, [%4];"
                 : "=r"(r0), "=r"(r1), "=r"(r2), "=r"(r3) : "r"(addr));
}
__device__ __forceinline__ void cpa16(uint32_t dst, const void* src, int srcsz) {
    asm volatile("cp.async.ca.shared.global [%0], [%1], 16, %2;"
                 :: "r"(dst), "l"(src), "r"(srcsz) : "memory");
}
#define CP_COMMIT() asm volatile("cp.async.commit_group;" ::: "memory")
#define CP_WAIT0()  asm volatile("cp.async.wait_group 0;" ::: "memory")
#define CP_WAIT1()  asm volatile("cp.async.wait_group 1;" ::: "memory")

// ---------------------------------------------------------------- embedding
__global__ void embed_kernel(const int* __restrict__ tok,
                             const float* __restrict__ wte,
                             const float* __restrict__ wpe,
                             float* __restrict__ x) {
    int idx = blockIdx.x * blockDim.x + threadIdx.x;
    if (idx >= TOKENS * EMB) return;
    int t = idx / EMB;
    int e = idx - t * EMB;
    x[idx] = wte[(size_t)tok[t] * EMB + e] + wpe[e];
}

// --------------------------------- layernorm (warp-per-row, fp16 output)
__global__ void ln_kernel(const float* __restrict__ x,
                          const float* __restrict__ w,
                          const float* __restrict__ bb,
                          __half* __restrict__ o) {
    const int row  = blockIdx.x * 8 + (threadIdx.x >> 5);
    const int lane = threadIdx.x & 31;
    const float* xr = x + (size_t)row * EMB;

    float4 v[6];
    float s = 0.f, sq = 0.f;
    #pragma unroll
    for (int i = 0; i < 6; i++) {
        v[i] = *(const float4*)(xr + lane * 4 + i * 128);
        s  += v[i].x + v[i].y + v[i].z + v[i].w;
        sq += v[i].x * v[i].x + v[i].y * v[i].y
            + v[i].z * v[i].z + v[i].w * v[i].w;
    }
    #pragma unroll
    for (int off = 16; off; off >>= 1) {
        s  += __shfl_xor_sync(0xffffffffu, s, off);
        sq += __shfl_xor_sync(0xffffffffu, sq, off);
    }
    const float mean = s * (1.f / EMB);
    const float rstd = rsqrtf(sq * (1.f / EMB) - mean * mean + 1e-5f);

    __half* orow = o + (size_t)row * EMB;
    #pragma unroll
    for (int i = 0; i < 6; i++) {
        const int c = lane * 4 + i * 128;
        float4 wv = *(const float4*)(w + c);
        float4 bv = *(const float4*)(bb + c);
        float r0 = (v[i].x - mean) * rstd * wv.x + bv.x;
        float r1 = (v[i].y - mean) * rstd * wv.y + bv.y;
        float r2 = (v[i].z - mean) * rstd * wv.z + bv.z;
        float r3 = (v[i].w - mean) * rstd * wv.w + bv.w;
        *(uint2*)(orow + c) = make_uint2(pack_f16(r0, r1), pack_f16(r2, r3));
    }
}

// --------------------------------------------- transpose + fp16 hi/lo split
__global__ void transpose_split_kernel(const float* __restrict__ in,
                                       __half* __restrict__ oh,
                                       __half* __restrict__ ol,
                                       int K, int N) {
    __shared__ float t[32][33];
    const size_t off = (size_t)blockIdx.z * K * N;
    int n0 = blockIdx.x * 32, k0 = blockIdx.y * 32;
    int x = threadIdx.x, y = threadIdx.y;
    #pragma unroll
    for (int i = 0; i < 32; i += 8)
        t[y + i][x] = in[off + (size_t)(k0 + y + i) * N + n0 + x];
    __syncthreads();
    #pragma unroll
    for (int i = 0; i < 32; i += 8) {
        float v = t[x][y + i];
        __half h = __float2half_rn(v);
        __half l = __float2half_rn(v - __half2float(h));
        size_t o = off + (size_t)(n0 + y + i) * K + k0 + x;
        oh[o] = h; ol[o] = l;
    }
}

// ------------------------------------------ transpose + fp16 (hi only)
__global__ void transpose_cvt_kernel(const float* __restrict__ in,
                                     __half* __restrict__ oh,
                                     int K, int N) {
    __shared__ float t[32][33];
    const size_t off = (size_t)blockIdx.z * K * N;
    int n0 = blockIdx.x * 32, k0 = blockIdx.y * 32;
    int x = threadIdx.x, y = threadIdx.y;
    #pragma unroll
    for (int i = 0; i < 32; i += 8)
        t[y + i][x] = in[off + (size_t)(k0 + y + i) * N + n0 + x];
    __syncthreads();
    #pragma unroll
    for (int i = 0; i < 32; i += 8)
        oh[off + (size_t)(n0 + y + i) * K + k0 + x] = __float2half_rn(t[x][y + i]);
}

// ---------------------------------------------- elementwise fp16 convert
__global__ void cvt_kernel(const float* __restrict__ in,
                           __half* __restrict__ oh, int n) {
    int i = blockIdx.x * blockDim.x + threadIdx.x;
    if (i >= n) return;
    oh[i] = __float2half_rn(in[i]);
}

// ------------------------------------------- fp16 mma.sync GEMM (k64 chunks)
// C[M,N] = A[M,K] @ B[N,K]^T.  A fp16 (producer-rounded).
// SPLIT: B = Bh + Bl (two MMAs) vs Bh only.  STG: cp.async pipeline depth.
// EPI 0: +bias -> half | EPI 1: +bias+res(fp32) -> float
// EPI 2: +bias+gelu -> half | EPI 4: plain, N-guard -> float (M-major raster)
#define BP 72
template <int EPI, int NT, bool SPLIT, int STG>
__global__ void __launch_bounds__(256, 2)
gemm_f16(const __half* __restrict__ Ah,
         const __half* __restrict__ Bh, const __half* __restrict__ Bl,
         const float* __restrict__ bias, const float* __restrict__ res,
         void* __restrict__ Cv, int M, int N, int K) {
    constexpr int ABUF = 128 * BP;
    constexpr int BBUF = NT * BP;
    constexpr int NBT  = NT / 32;

    extern __shared__ __half sm[];
    __half* sA  = sm;                       // STG x ABUF
    __half* sBh = sm + STG * ABUF;          // STG x BBUF
    __half* sBl = sBh + STG * BBUF;         // STG x BBUF (SPLIT only)
    const uint32_t uA  = (uint32_t)__cvta_generic_to_shared(sA);
    const uint32_t uBh = (uint32_t)__cvta_generic_to_shared(sBh);
    const uint32_t uBl = (uint32_t)__cvta_generic_to_shared(sBl);

    const int tid  = threadIdx.x;
    const int wid  = tid >> 5;
    const int lane = tid & 31;
    const int grp  = lane >> 2;
    const int tig  = lane & 3;
    // EPI 4 (LM head): M-major raster — consecutive CTAs share the B tile.
    const int bm = (EPI == 4 ? blockIdx.x : blockIdx.y) * 128;
    const int bn = (EPI == 4 ? blockIdx.y : blockIdx.x) * NT;
    const int wm0 = (wid & 1) * 64;
    const int wn0 = (wid >> 1) * (NT / 4);

    const int a_row = (lane & 15);
    const int a_k   = (lane >> 4) << 3;
    const int b_row = (lane & 7) + ((lane >> 4) << 3);
    const int b_k   = ((lane >> 3) & 1) << 3;
    const int b2_row = lane & 7;
    const int b2_k   = ((lane >> 3) & 1) << 3;

    float cf[4][NBT][4];
    #pragma unroll
    for (int i = 0; i < 4; i++)
        #pragma unroll
        for (int j = 0; j < NBT; j++)
            #pragma unroll
            for (int r = 0; r < 4; r++) cf[i][j][r] = 0.f;

    const int KC = K >> 6;

    auto stage = [&](int k0, int p) {
        #pragma unroll
        for (int ps = 0; ps < 4; ps++) {
            int s = tid + ps * 256;
            int row = s >> 3;
            int c16 = (s & 7) * 8;
            uint32_t doff = (uint32_t)(p * ABUF + row * BP + c16) * 2;
            cpa16(uA + doff, Ah + (size_t)(bm + row) * K + k0 + c16, 16);
        }
        #pragma unroll
        for (int ps = 0; ps < NT / 32; ps++) {
            int s = tid + ps * 256;
            int row = s >> 3;
            int c16 = (s & 7) * 8;
            int gr = bn + row, sz = 16;
            if (EPI == 4 && gr >= N) { gr = 0; sz = 0; }
            uint32_t doff = (uint32_t)(p * BBUF + row * BP + c16) * 2;
            cpa16(uBh + doff, Bh + (size_t)gr * K + k0 + c16, sz);
            if (SPLIT)
                cpa16(uBl + doff, Bl + (size_t)gr * K + k0 + c16, sz);
        }
        CP_COMMIT();
    };

    #pragma unroll
    for (int s = 0; s < STG - 1; s++) stage(s << 6, s);

    for (int c = 0; c < KC; c++) {
        const int p = c % STG;
        if (STG == 2) { CP_WAIT0(); }
        else          { if (c + 1 < KC) CP_WAIT1(); else CP_WAIT0(); }
        __syncthreads();
        const int nc = c + STG - 1;
        if (nc < KC) stage(nc << 6, nc % STG);

        const uint32_t bufA  = uA  + (uint32_t)(p * ABUF) * 2;
        const uint32_t bufBh = uBh + (uint32_t)(p * BBUF) * 2;
        const uint32_t bufBl = uBl + (uint32_t)(p * BBUF) * 2;
        #pragma unroll
        for (int ks = 0; ks < 4; ks++) {
            const int k0 = ks * 16;
            uint32_t bh[NBT][2], bl[NBT][2];
            uint32_t bo = (uint32_t)((wn0 + b_row) * BP + k0 + b_k) * 2;
            #pragma unroll
            for (int g = 0; g < NBT / 2; g++) {
                ldmx4(bh[2 * g][0], bh[2 * g][1], bh[2 * g + 1][0], bh[2 * g + 1][1],
                      bufBh + bo + (uint32_t)(g * 16 * BP) * 2);
                if (SPLIT)
                    ldmx4(bl[2 * g][0], bl[2 * g][1], bl[2 * g + 1][0], bl[2 * g + 1][1],
                          bufBl + bo + (uint32_t)(g * 16 * BP) * 2);
            }
            if (NBT & 1) {
                uint32_t bo2 = (uint32_t)((wn0 + (NBT - 1) * 8 + b2_row) * BP + k0 + b2_k) * 2;
                ldmx2(bh[NBT - 1][0], bh[NBT - 1][1], bufBh + bo2);
                if (SPLIT)
                    ldmx2(bl[NBT - 1][0], bl[NBT - 1][1], bufBl + bo2);
            }
            #pragma unroll
            for (int mt = 0; mt < 4; mt++) {
                uint32_t a[4];
                uint32_t ao = (uint32_t)((wm0 + mt * 16 + a_row) * BP + k0 + a_k) * 2;
                ldmx4(a[0], a[1], a[2], a[3], bufA + ao);
                #pragma unroll
                for (int nt = 0; nt < NBT; nt++) {
                    mma_f16(cf[mt][nt], a, bh[nt]);
                    if (SPLIT) mma_f16(cf[mt][nt], a, bl[nt]);
                }
            }
        }
    }

    // ---------------- epilogue ----------------
    #pragma unroll
    for (int mt = 0; mt < 4; mt++) {
        #pragma unroll
        for (int half = 0; half < 2; half++) {
            const int row = bm + wm0 + mt * 16 + grp + half * 8;
            #pragma unroll
            for (int nt = 0; nt < NBT; nt++) {
                const int col = bn + wn0 + nt * 8 + 2 * tig;
                float v0 = cf[mt][nt][half * 2 + 0];
                float v1 = cf[mt][nt][half * 2 + 1];
                if (EPI == 4) {
                    float* C = (float*)Cv;
                    if (col < N)     C[(size_t)row * N + col]     = v0;
                    if (col + 1 < N) C[(size_t)row * N + col + 1] = v1;
                } else {
                    v0 += bias[col];
                    v1 += bias[col + 1];
                    if (EPI == 1) {
                        const float* rp = res + (size_t)row * N + col;
                        v0 += rp[0]; v1 += rp[1];
                        *(float2*)((float*)Cv + (size_t)row * N + col) = make_float2(v0, v1);
                    } else {
                        if (EPI == 2) { v0 = gelu_f(v0); v1 = gelu_f(v1); }
                        *(uint32_t*)((__half*)Cv + (size_t)row * N + col) = pack_f16(v0, v1);
                    }
                }
            }
        }
    }
}

// ------------------------------------ fp16 mma.sync flash attention (v3)
// Paired Q tiles (x and NT-1-x) per block: constant work per block.
#define APT 72
#define ATILE (64 * APT)
__global__ void __launch_bounds__(128)
attn_mma(const __half* __restrict__ qkv, __half* __restrict__ y) {
    extern __shared__ __half sh[];
    __half* sQ = sh;
    __half* sK = sh + ATILE;
    __half* sV = sh + 3 * ATILE;
    const uint32_t uQ = (uint32_t)__cvta_generic_to_shared(sQ);
    const uint32_t uK = (uint32_t)__cvta_generic_to_shared(sK);
    const uint32_t uV = (uint32_t)__cvta_generic_to_shared(sV);

    const int NT = SEQ / 64;
    const int h = blockIdx.y, b = blockIdx.z;
    const int tid  = threadIdx.x;
    const int wid  = tid >> 5;
    const int lane = tid & 31;
    const int grp  = lane >> 2;
    const int tig  = lane & 3;
    const float scale = 0.036084391824351615f;  // 1/sqrt(768)

    const int a_row = lane & 15;
    const int a_k   = (lane >> 4) << 3;
    const int b_row = (lane & 7) + ((lane >> 4) << 3);
    const int b_k   = ((lane >> 3) & 1) << 3;

    auto stageKV = [&](int ks, int p) {
        #pragma unroll
        for (int ps = 0; ps < 4; ps++) {
            int s = tid + ps * 128;
            int row = s >> 3;
            int ch = (s & 7) * 8;
            const __half* base = qkv + ((size_t)b * SEQ + (size_t)ks * 64 + row) * QKVDIM
                               + h * HDIM + ch;
            uint32_t doff = (uint32_t)(p * ATILE + row * APT + ch) * 2;
            cpa16(uK + doff, base + EMB, 16);
            cpa16(uV + doff, base + 2 * EMB, 16);
        }
        CP_COMMIT();
    };

    #pragma unroll 1
    for (int qi = 0; qi < 2; qi++) {
        const int tq = qi == 0 ? (int)blockIdx.x : NT - 1 - (int)blockIdx.x;

        __syncthreads();
        #pragma unroll
        for (int ps = 0; ps < 4; ps++) {
            int s = tid + ps * 128;
            int row = s >> 3;
            int ch = (s & 7) * 8;
            cpa16(uQ + (uint32_t)(row * APT + ch) * 2,
                  qkv + ((size_t)b * SEQ + (size_t)tq * 64 + row) * QKVDIM + h * HDIM + ch, 16);
        }
        CP_COMMIT();
        stageKV(0, 0);
        CP_WAIT0();
        __syncthreads();

        uint32_t qf[4][4];
        #pragma unroll
        for (int kt = 0; kt < 4; kt++) {
            uint32_t ao = (uint32_t)((wid * 16 + a_row) * APT + kt * 16 + a_k) * 2;
            ldmx4(qf[kt][0], qf[kt][1], qf[kt][2], qf[kt][3], uQ + ao);
        }

        float o[8][4];
        #pragma unroll
        for (int nt = 0; nt < 8; nt++)
            #pragma unroll
            for (int r = 0; r < 4; r++) o[nt][r] = 0.f;
        float m0 = -1e30f, m1 = -1e30f, l0 = 0.f, l1 = 0.f;

        const int row_g0 = tq * 64 + wid * 16 + grp;
        const int row_g1 = row_g0 + 8;

        for (int ks = 0; ks <= tq; ks++) {
            const int p = ks & 1;
            if (ks > 0) { CP_WAIT0(); __syncthreads(); }
            if (ks + 1 <= tq) stageKV(ks + 1, 1 - p);

            const uint32_t bufK = uK + (uint32_t)(p * ATILE) * 2;
            const uint32_t bufV = uV + (uint32_t)(p * ATILE) * 2;

            float s[8][4];
            #pragma unroll
            for (int nt = 0; nt < 8; nt++)
                #pragma unroll
                for (int r = 0; r < 4; r++) s[nt][r] = 0.f;
            #pragma unroll
            for (int kt = 0; kt < 4; kt++) {
                #pragma unroll
                for (int ntp = 0; ntp < 4; ntp++) {
                    uint32_t kb[2][2];
                    uint32_t bo = (uint32_t)((ntp * 16 + b_row) * APT + kt * 16 + b_k) * 2;
                    ldmx4(kb[0][0], kb[0][1], kb[1][0], kb[1][1], bufK + bo);
                    mma_f16(s[2 * ntp + 0], qf[kt], kb[0]);
                    mma_f16(s[2 * ntp + 1], qf[kt], kb[1]);
                }
            }

            const bool diag = (ks == tq);
            #pragma unroll
            for (int nt = 0; nt < 8; nt++) {
                int c = ks * 64 + nt * 8 + 2 * tig;
                #pragma unroll
                for (int r = 0; r < 4; r++) s[nt][r] *= scale;
                if (diag) {
                    if (c > row_g0)     s[nt][0] = -1e30f;
                    if (c + 1 > row_g0) s[nt][1] = -1e30f;
                    if (c > row_g1)     s[nt][2] = -1e30f;
                    if (c + 1 > row_g1) s[nt][3] = -1e30f;
                }
            }

            float t0 = -1e30f, t1 = -1e30f;
            #pragma unroll
            for (int nt = 0; nt < 8; nt++) {
                t0 = fmaxf(t0, fmaxf(s[nt][0], s[nt][1]));
                t1 = fmaxf(t1, fmaxf(s[nt][2], s[nt][3]));
            }
            #pragma unroll
            for (int off = 1; off < 4; off <<= 1) {
                t0 = fmaxf(t0, __shfl_xor_sync(0xffffffffu, t0, off));
                t1 = fmaxf(t1, __shfl_xor_sync(0xffffffffu, t1, off));
            }
            float nm0 = fmaxf(m0, t0), nm1 = fmaxf(m1, t1);
            float cr0 = __expf(m0 - nm0), cr1 = __expf(m1 - nm1);
            m0 = nm0; m1 = nm1;
            float rs0 = 0.f, rs1 = 0.f;
            uint32_t p01[8], p23[8];
            #pragma unroll
            for (int nt = 0; nt < 8; nt++) {
                float e0 = __expf(s[nt][0] - nm0);
                float e1 = __expf(s[nt][1] - nm0);
                float e2 = __expf(s[nt][2] - nm1);
                float e3 = __expf(s[nt][3] - nm1);
                rs0 += e0 + e1; rs1 += e2 + e3;
                p01[nt] = pack_f16(e0, e1);
                p23[nt] = pack_f16(e2, e3);
            }
            #pragma unroll
            for (int off = 1; off < 4; off <<= 1) {
                rs0 += __shfl_xor_sync(0xffffffffu, rs0, off);
                rs1 += __shfl_xor_sync(0xffffffffu, rs1, off);
            }
            l0 = l0 * cr0 + rs0;
            l1 = l1 * cr1 + rs1;
            #pragma unroll
            for (int nt = 0; nt < 8; nt++) {
                o[nt][0] *= cr0; o[nt][1] *= cr0;
                o[nt][2] *= cr1; o[nt][3] *= cr1;
            }

            #pragma unroll
            for (int kt = 0; kt < 4; kt++) {
                uint32_t a[4] = { p01[2 * kt], p23[2 * kt], p01[2 * kt + 1], p23[2 * kt + 1] };
                #pragma unroll
                for (int ntp = 0; ntp < 4; ntp++) {
                    uint32_t vb[2][2];
                    uint32_t vo = (uint32_t)((kt * 16 + a_row) * APT + ntp * 16 + a_k) * 2;
                    ldmx4t(vb[0][0], vb[0][1], vb[1][0], vb[1][1], bufV + vo);
                    mma_f16(o[2 * ntp + 0], a, vb[0]);
                    mma_f16(o[2 * ntp + 1], a, vb[1]);
                }
            }
        }

        float inv0 = 1.f / l0, inv1 = 1.f / l1;
        __half* y0 = y + ((size_t)b * SEQ + (size_t)tq * 64 + wid * 16 + grp) * EMB + h * HDIM;
        __half* y1 = y0 + 8 * EMB;
        #pragma unroll
        for (int nt = 0; nt < 8; nt++) {
            int c = nt * 8 + 2 * tig;
            *(uint32_t*)(y0 + c) = pack_f16(o[nt][0] * inv0, o[nt][1] * inv0);
            *(uint32_t*)(y1 + c) = pack_f16(o[nt][2] * inv1, o[nt][3] * inv1);
        }
    }
}

// -------------------------------------------------------------------- launch
extern "C" void kernel_launch(void* const* d_in, const int* in_sizes, int n_in,
                              void* d_out, int out_size) {
    const int*   tokens = (const int*)  d_in[0];
    const float* wte    = (const float*)d_in[1];
    const float* wpe    = (const float*)d_in[2];
    const float* ln1w   = (const float*)d_in[3];
    const float* ln1b   = (const float*)d_in[4];
    const float* qkvw   = (const float*)d_in[5];
    const float* qkvb   = (const float*)d_in[6];
    const float* atpw   = (const float*)d_in[7];
    const float* atpb   = (const float*)d_in[8];
    const float* ln2w   = (const float*)d_in[9];
    const float* ln2b   = (const float*)d_in[10];
    const float* fcw    = (const float*)d_in[11];
    const float* fcb    = (const float*)d_in[12];
    const float* fpw    = (const float*)d_in[13];
    const float* fpb    = (const float*)d_in[14];
    const float* lnfw   = (const float*)d_in[15];
    const float* lnfb   = (const float*)d_in[16];
    const float* lmw    = (const float*)d_in[17];
    float* out = (float*)d_out;

    float* px;
    __half *pah, *pqkvh, *pyh, *pmh;
    __half *qh, *ah, *fh, *fl, *ph, *lh;
    cudaGetSymbolAddress((void**)&px,    g_x);
    cudaGetSymbolAddress((void**)&pah,   g_ah);
    cudaGetSymbolAddress((void**)&pqkvh, g_qkvh);
    cudaGetSymbolAddress((void**)&pyh,   g_yh);
    cudaGetSymbolAddress((void**)&pmh,   g_mh);
    cudaGetSymbolAddress((void**)&qh, g_qkvH);
    cudaGetSymbolAddress((void**)&ah, g_atpH);
    cudaGetSymbolAddress((void**)&fh, g_fcH);  cudaGetSymbolAddress((void**)&fl, g_fcL);
    cudaGetSymbolAddress((void**)&ph, g_fpH);
    cudaGetSymbolAddress((void**)&lh, g_lmH);

    const int smem128s2 = (2 * 128 * BP + 4 * 128 * BP) * 2;  // 110592 (fc, split, 2-stage)
    const int smem96s1  = (3 * 128 * BP + 3 * 96 * BP) * 2;   // 96768  (proj/fp, 3-stage)
    const int smem128s1 = (2 * 128 * BP + 2 * 128 * BP) * 2;  // 73728  (qkv/lm, 2-stage)
    cudaFuncSetAttribute((gemm_f16<0, 128, false, 2>), cudaFuncAttributeMaxDynamicSharedMemorySize, smem128s1);
    cudaFuncSetAttribute((gemm_f16<2, 128, true, 2>),  cudaFuncAttributeMaxDynamicSharedMemorySize, smem128s2);
    cudaFuncSetAttribute((gemm_f16<1, 96, false, 3>),  cudaFuncAttributeMaxDynamicSharedMemorySize, smem96s1);
    cudaFuncSetAttribute((gemm_f16<4, 128, false, 2>), cudaFuncAttributeMaxDynamicSharedMemorySize, smem128s1);

    const int asmem = 5 * ATILE * sizeof(__half);  // 46080
    cudaFuncSetAttribute(attn_mma, cudaFuncAttributeMaxDynamicSharedMemorySize, asmem);

    dim3 tb(32, 8);
    transpose_cvt_kernel<<<dim3(QKVDIM / 32, EMB / 32, NLAYER), tb>>>(qkvw, qh, EMB, QKVDIM);
    transpose_cvt_kernel<<<dim3(EMB / 32,    EMB / 32, NLAYER), tb>>>(atpw, ah, EMB, EMB);
    transpose_split_kernel<<<dim3(FFDIM / 32,  EMB / 32, NLAYER), tb>>>(fcw,  fh, fl, EMB, FFDIM);
    transpose_cvt_kernel<<<dim3(EMB / 32,  FFDIM / 32, NLAYER), tb>>>(fpw,  ph, FFDIM, EMB);
    cvt_kernel<<<(VOCAB * EMB + 255) / 256, 256>>>(lmw, lh, VOCAB * EMB);

    embed_kernel<<<(TOKENS * EMB + 255) / 256, 256>>>(tokens, wte, wpe, px);

    for (int i = 0; i < NLAYER; i++) {
        ln_kernel<<<TOKENS / 8, 256>>>(px, ln1w + i * EMB, ln1b + i * EMB, pah);

        gemm_f16<0, 128, false, 2><<<dim3(QKVDIM / 128, TOKENS / 128), 256, smem128s1>>>(
            pah, qh + (size_t)i * QKVDIM * EMB, nullptr,
            qkvb + i * QKVDIM, nullptr, pqkvh, TOKENS, QKVDIM, EMB);

        attn_mma<<<dim3(SEQ / 128, NHEAD, NBATCH), 128, asmem>>>(pqkvh, pyh);

        gemm_f16<1, 96, false, 3><<<dim3(EMB / 96, TOKENS / 128), 256, smem96s1>>>(
            pyh, ah + (size_t)i * EMB * EMB, nullptr,
            atpb + i * EMB, px, px, TOKENS, EMB, EMB);

        ln_kernel<<<TOKENS / 8, 256>>>(px, ln2w + i * EMB, ln2b + i * EMB, pah);

        gemm_f16<2, 128, true, 2><<<dim3(FFDIM / 128, TOKENS / 128), 256, smem128s2>>>(
            pah, fh + (size_t)i * FFDIM * EMB, fl + (size_t)i * FFDIM * EMB,
            fcb + i * FFDIM, nullptr, pmh, TOKENS, FFDIM, EMB);

        gemm_f16<1, 96, false, 3><<<dim3(EMB / 96, TOKENS / 128), 256, smem96s1>>>(
            pmh, ph + (size_t)i * EMB * FFDIM, nullptr,
            fpb + i * EMB, px, px, TOKENS, EMB, FFDIM);
    }

    ln_kernel<<<TOKENS / 8, 256>>>(px, lnfw, lnfb, pah);

    gemm_f16<4, 128, false, 2><<<dim3(TOKENS / 128, (VOCAB + 127) / 128), 256, smem128s1>>>(
        pah, lh, nullptr, nullptr, nullptr, out, TOKENS, VOCAB, EMB);
}

// round 17
// speedup vs baseline: 1.0605x; 1.0053x over previous
#include <cuda_runtime.h>
#include <cuda_fp16.h>
#include <math.h>
#include <stdint.h>

#define TOKENS 4096
#define EMB    768
#define NLAYER 12
#define NHEAD  12
#define HDIM   64
#define SEQ    1024
#define NBATCH 4
#define VOCAB  50257
#define FFDIM  3072
#define QKVDIM 2304

// -------------------- scratch (static device globals; no allocation) --------
__device__ float  g_x  [TOKENS * EMB];
__device__ __half g_ah [TOKENS * EMB];
__device__ __half g_qkvh[TOKENS * QKVDIM];
__device__ __half g_yh [TOKENS * EMB];
__device__ __half g_mh [TOKENS * FFDIM];
__device__ __half g_qkvH[(size_t)NLAYER * QKVDIM * EMB];
__device__ __half g_atpH[(size_t)NLAYER * EMB * EMB];
__device__ __half g_fcH [(size_t)NLAYER * FFDIM * EMB];
__device__ __half g_fcL [(size_t)NLAYER * FFDIM * EMB];
__device__ __half g_fpH [(size_t)NLAYER * EMB * FFDIM];
__device__ __half g_lmH [(size_t)VOCAB * EMB];

// ------------------------------------------------------------- helpers
__device__ __forceinline__ float gelu_f(float x) {
    float x3 = x * x * x;
    return 0.5f * x * (1.f + tanhf(0.7978845608028654f * (x + 0.044715f * x3)));
}
__device__ __forceinline__ uint32_t pack_f16(float x0, float x1) {
    uint32_t u;
    asm("{.reg .b16 l,h; cvt.rn.f16.f32 l,%1; cvt.rn.f16.f32 h,%2; mov.b32 %0,{l,h};}"
        : "=r"(u) : "f"(x0), "f"(x1));
    return u;
}
__device__ __forceinline__ void mma_f16(float* c, const uint32_t* a, const uint32_t* b) {
    asm volatile(
        "mma.sync.aligned.m16n8k16.row.col.f32.f16.f16.f32 "
        "{%0,%1,%2,%3}, {%4,%5,%6,%7}, {%8,%9}, {%0,%1,%2,%3};"
        : "+f"(c[0]), "+f"(c[1]), "+f"(c[2]), "+f"(c[3])
        : "r"(a[0]), "r"(a[1]), "r"(a[2]), "r"(a[3]), "r"(b[0]), "r"(b[1]));
}
__device__ __forceinline__ void ldmx4(uint32_t& r0, uint32_t& r1,
                                      uint32_t& r2, uint32_t& r3, uint32_t addr) {
    asm volatile("ldmatrix.sync.aligned.m8n8.x4.shared.b16 {%0,%1,%2,%3}, [%4];"
                 : "=r"(r0), "=r"(r1), "=r"(r2), "=r"(r3) : "r"(addr));
}
__device__ __forceinline__ void ldmx2(uint32_t& r0, uint32_t& r1, uint32_t addr) {
    asm volatile("ldmatrix.sync.aligned.m8n8.x2.shared.b16 {%0,%1}, [%2];"
                 : "=r"(r0), "=r"(r1) : "r"(addr));
}
__device__ __forceinline__ void ldmx4t(uint32_t& r0, uint32_t& r1,
                                       uint32_t& r2, uint32_t& r3, uint32_t addr) {
    asm volatile("ldmatrix.sync.aligned.m8n8.x4.trans.shared.b16 {%0,%1,%2,%3}, [%4];"
                 : "=r"(r0), "=r"(r1), "=r"(r2), "=r"(r3) : "r"(addr));
}
__device__ __forceinline__ void cpa16(uint32_t dst, const void* src, int srcsz) {
    asm volatile("cp.async.ca.shared.global [%0], [%1], 16, %2;"
                 :: "r"(dst), "l"(src), "r"(srcsz) : "memory");
}
#define CP_COMMIT() asm volatile("cp.async.commit_group;" ::: "memory")
#define CP_WAIT0()  asm volatile("cp.async.wait_group 0;" ::: "memory")

// ---------------------------------------------------------------- embedding
__global__ void embed_kernel(const int* __restrict__ tok,
                             const float* __restrict__ wte,
                             const float* __restrict__ wpe,
                             float* __restrict__ x) {
    int idx = blockIdx.x * blockDim.x + threadIdx.x;
    if (idx >= TOKENS * EMB) return;
    int t = idx / EMB;
    int e = idx - t * EMB;
    x[idx] = wte[(size_t)tok[t] * EMB + e] + wpe[e];
}

// --------------------------------- layernorm (warp-per-row, fp16 output)
__global__ void ln_kernel(const float* __restrict__ x,
                          const float* __restrict__ w,
                          const float* __restrict__ bb,
                          __half* __restrict__ o) {
    const int row  = blockIdx.x * 8 + (threadIdx.x >> 5);
    const int lane = threadIdx.x & 31;
    const float* xr = x + (size_t)row * EMB;

    float4 v[6];
    float s = 0.f, sq = 0.f;
    #pragma unroll
    for (int i = 0; i < 6; i++) {
        v[i] = *(const float4*)(xr + lane * 4 + i * 128);
        s  += v[i].x + v[i].y + v[i].z + v[i].w;
        sq += v[i].x * v[i].x + v[i].y * v[i].y
            + v[i].z * v[i].z + v[i].w * v[i].w;
    }
    #pragma unroll
    for (int off = 16; off; off >>= 1) {
        s  += __shfl_xor_sync(0xffffffffu, s, off);
        sq += __shfl_xor_sync(0xffffffffu, sq, off);
    }
    const float mean = s * (1.f / EMB);
    const float rstd = rsqrtf(sq * (1.f / EMB) - mean * mean + 1e-5f);

    __half* orow = o + (size_t)row * EMB;
    #pragma unroll
    for (int i = 0; i < 6; i++) {
        const int c = lane * 4 + i * 128;
        float4 wv = *(const float4*)(w + c);
        float4 bv = *(const float4*)(bb + c);
        float r0 = (v[i].x - mean) * rstd * wv.x + bv.x;
        float r1 = (v[i].y - mean) * rstd * wv.y + bv.y;
        float r2 = (v[i].z - mean) * rstd * wv.z + bv.z;
        float r3 = (v[i].w - mean) * rstd * wv.w + bv.w;
        *(uint2*)(orow + c) = make_uint2(pack_f16(r0, r1), pack_f16(r2, r3));
    }
}

// --------------------------------------------- transpose + fp16 hi/lo split
__global__ void transpose_split_kernel(const float* __restrict__ in,
                                       __half* __restrict__ oh,
                                       __half* __restrict__ ol,
                                       int K, int N) {
    __shared__ float t[32][33];
    const size_t off = (size_t)blockIdx.z * K * N;
    int n0 = blockIdx.x * 32, k0 = blockIdx.y * 32;
    int x = threadIdx.x, y = threadIdx.y;
    #pragma unroll
    for (int i = 0; i < 32; i += 8)
        t[y + i][x] = in[off + (size_t)(k0 + y + i) * N + n0 + x];
    __syncthreads();
    #pragma unroll
    for (int i = 0; i < 32; i += 8) {
        float v = t[x][y + i];
        __half h = __float2half_rn(v);
        __half l = __float2half_rn(v - __half2float(h));
        size_t o = off + (size_t)(n0 + y + i) * K + k0 + x;
        oh[o] = h; ol[o] = l;
    }
}

// ------------------------------------------ transpose + fp16 (hi only)
__global__ void transpose_cvt_kernel(const float* __restrict__ in,
                                     __half* __restrict__ oh,
                                     int K, int N) {
    __shared__ float t[32][33];
    const size_t off = (size_t)blockIdx.z * K * N;
    int n0 = blockIdx.x * 32, k0 = blockIdx.y * 32;
    int x = threadIdx.x, y = threadIdx.y;
    #pragma unroll
    for (int i = 0; i < 32; i += 8)
        t[y + i][x] = in[off + (size_t)(k0 + y + i) * N + n0 + x];
    __syncthreads();
    #pragma unroll
    for (int i = 0; i < 32; i += 8)
        oh[off + (size_t)(n0 + y + i) * K + k0 + x] = __float2half_rn(t[x][y + i]);
}

// ---------------------------------------------- elementwise fp16 convert
__global__ void cvt_kernel(const float* __restrict__ in,
                           __half* __restrict__ oh, int n) {
    int i = blockIdx.x * blockDim.x + threadIdx.x;
    if (i >= n) return;
    oh[i] = __float2half_rn(in[i]);
}

// ------------------------------------------- fp16 mma.sync GEMM (k64 chunks)
// C[M,N] = A[M,K] @ B[N,K]^T.  A fp16 (producer-rounded).  2-stage pipeline.
// SPLIT: B = Bh + Bl (two MMAs) vs Bh only.
// EPI 0: +bias -> half | EPI 1: +bias+res(fp32) -> float
// EPI 2: +bias+gelu -> half | EPI 4: plain, N-guard -> float (M-major raster)
#define BP 72
template <int EPI, int NT, bool SPLIT>
__global__ void __launch_bounds__(256, 2)
gemm_f16(const __half* __restrict__ Ah,
         const __half* __restrict__ Bh, const __half* __restrict__ Bl,
         const float* __restrict__ bias, const float* __restrict__ res,
         void* __restrict__ Cv, int M, int N, int K) {
    constexpr int ABUF = 128 * BP;
    constexpr int BBUF = NT * BP;
    constexpr int NBT  = NT / 32;

    extern __shared__ __half sm[];
    __half* sA  = sm;
    __half* sBh = sm + 2 * ABUF;
    __half* sBl = sBh + 2 * BBUF;
    const uint32_t uA  = (uint32_t)__cvta_generic_to_shared(sA);
    const uint32_t uBh = (uint32_t)__cvta_generic_to_shared(sBh);
    const uint32_t uBl = (uint32_t)__cvta_generic_to_shared(sBl);

    const int tid  = threadIdx.x;
    const int wid  = tid >> 5;
    const int lane = tid & 31;
    const int grp  = lane >> 2;
    const int tig  = lane & 3;
    const int bm = (EPI == 4 ? blockIdx.x : blockIdx.y) * 128;
    const int bn = (EPI == 4 ? blockIdx.y : blockIdx.x) * NT;
    const int wm0 = (wid & 1) * 64;
    const int wn0 = (wid >> 1) * (NT / 4);

    const int a_row = (lane & 15);
    const int a_k   = (lane >> 4) << 3;
    const int b_row = (lane & 7) + ((lane >> 4) << 3);
    const int b_k   = ((lane >> 3) & 1) << 3;
    const int b2_row = lane & 7;
    const int b2_k   = ((lane >> 3) & 1) << 3;

    float cf[4][NBT][4];
    #pragma unroll
    for (int i = 0; i < 4; i++)
        #pragma unroll
        for (int j = 0; j < NBT; j++)
            #pragma unroll
            for (int r = 0; r < 4; r++) cf[i][j][r] = 0.f;

    const int KC = K >> 6;

    auto stage = [&](int k0, int p) {
        #pragma unroll
        for (int ps = 0; ps < 4; ps++) {
            int s = tid + ps * 256;
            int row = s >> 3;
            int c16 = (s & 7) * 8;
            uint32_t doff = (uint32_t)(p * ABUF + row * BP + c16) * 2;
            cpa16(uA + doff, Ah + (size_t)(bm + row) * K + k0 + c16, 16);
        }
        #pragma unroll
        for (int ps = 0; ps < NT / 32; ps++) {
            int s = tid + ps * 256;
            int row = s >> 3;
            int c16 = (s & 7) * 8;
            int gr = bn + row, sz = 16;
            if (EPI == 4 && gr >= N) { gr = 0; sz = 0; }
            uint32_t doff = (uint32_t)(p * BBUF + row * BP + c16) * 2;
            cpa16(uBh + doff, Bh + (size_t)gr * K + k0 + c16, sz);
            if (SPLIT)
                cpa16(uBl + doff, Bl + (size_t)gr * K + k0 + c16, sz);
        }
        CP_COMMIT();
    };

    stage(0, 0);

    for (int c = 0; c < KC; c++) {
        const int p = c & 1;
        CP_WAIT0();
        __syncthreads();
        if (c + 1 < KC) stage((c + 1) << 6, 1 - p);

        const uint32_t bufA  = uA  + (uint32_t)(p * ABUF) * 2;
        const uint32_t bufBh = uBh + (uint32_t)(p * BBUF) * 2;
        const uint32_t bufBl = uBl + (uint32_t)(p * BBUF) * 2;
        #pragma unroll
        for (int ks = 0; ks < 4; ks++) {
            const int k0 = ks * 16;
            uint32_t bh[NBT][2], bl[NBT][2];
            uint32_t bo = (uint32_t)((wn0 + b_row) * BP + k0 + b_k) * 2;
            #pragma unroll
            for (int g = 0; g < NBT / 2; g++) {
                ldmx4(bh[2 * g][0], bh[2 * g][1], bh[2 * g + 1][0], bh[2 * g + 1][1],
                      bufBh + bo + (uint32_t)(g * 16 * BP) * 2);
                if (SPLIT)
                    ldmx4(bl[2 * g][0], bl[2 * g][1], bl[2 * g + 1][0], bl[2 * g + 1][1],
                          bufBl + bo + (uint32_t)(g * 16 * BP) * 2);
            }
            if (NBT & 1) {
                uint32_t bo2 = (uint32_t)((wn0 + (NBT - 1) * 8 + b2_row) * BP + k0 + b2_k) * 2;
                ldmx2(bh[NBT - 1][0], bh[NBT - 1][1], bufBh + bo2);
                if (SPLIT)
                    ldmx2(bl[NBT - 1][0], bl[NBT - 1][1], bufBl + bo2);
            }
            #pragma unroll
            for (int mt = 0; mt < 4; mt++) {
                uint32_t a[4];
                uint32_t ao = (uint32_t)((wm0 + mt * 16 + a_row) * BP + k0 + a_k) * 2;
                ldmx4(a[0], a[1], a[2], a[3], bufA + ao);
                #pragma unroll
                for (int nt = 0; nt < NBT; nt++) {
                    mma_f16(cf[mt][nt], a, bh[nt]);
                    if (SPLIT) mma_f16(cf[mt][nt], a, bl[nt]);
                }
            }
        }
    }

    // ---------------- epilogue ----------------
    #pragma unroll
    for (int mt = 0; mt < 4; mt++) {
        #pragma unroll
        for (int half = 0; half < 2; half++) {
            const int row = bm + wm0 + mt * 16 + grp + half * 8;
            #pragma unroll
            for (int nt = 0; nt < NBT; nt++) {
                const int col = bn + wn0 + nt * 8 + 2 * tig;
                float v0 = cf[mt][nt][half * 2 + 0];
                float v1 = cf[mt][nt][half * 2 + 1];
                if (EPI == 4) {
                    float* C = (float*)Cv;
                    if (col < N)     C[(size_t)row * N + col]     = v0;
                    if (col + 1 < N) C[(size_t)row * N + col + 1] = v1;
                } else {
                    v0 += bias[col];
                    v1 += bias[col + 1];
                    if (EPI == 1) {
                        const float* rp = res + (size_t)row * N + col;
                        v0 += rp[0]; v1 += rp[1];
                        *(float2*)((float*)Cv + (size_t)row * N + col) = make_float2(v0, v1);
                    } else {
                        if (EPI == 2) { v0 = gelu_f(v0); v1 = gelu_f(v1); }
                        *(uint32_t*)((__half*)Cv + (size_t)row * N + col) = pack_f16(v0, v1);
                    }
                }
            }
        }
    }
}

// ------------------------------------ fp16 mma.sync flash attention (v5)
// 128-row Q tiles, 8 warps (256 threads). Paired complementary tiles
// (T and 7-T) per block: constant 18 KV-tile iterations; K/V staging
// traffic 0.53x of the 64-row scheme at identical MMA totals.
#define APT 72
#define QTILE (128 * APT)
#define KTILE (64 * APT)
__global__ void __launch_bounds__(256)
attn_mma(const __half* __restrict__ qkv, __half* __restrict__ y) {
    extern __shared__ __half sh[];
    __half* sQ = sh;                  // [128][APT]
    __half* sK = sh + QTILE;          // 2 x [64][APT]
    __half* sV = sh + QTILE + 2 * KTILE;
    const uint32_t uQ = (uint32_t)__cvta_generic_to_shared(sQ);
    const uint32_t uK = (uint32_t)__cvta_generic_to_shared(sK);
    const uint32_t uV = (uint32_t)__cvta_generic_to_shared(sV);

    const int NT2 = SEQ / 128;        // 8 Q tiles of 128 rows
    const int h = blockIdx.y, b = blockIdx.z;
    const int tid  = threadIdx.x;
    const int wid  = tid >> 5;        // 0..7
    const int lane = tid & 31;
    const int grp  = lane >> 2;
    const int tig  = lane & 3;
    const float scale = 0.036084391824351615f;  // 1/sqrt(768)

    const int a_row = lane & 15;
    const int a_k   = (lane >> 4) << 3;
    const int b_row = (lane & 7) + ((lane >> 4) << 3);
    const int b_k   = ((lane >> 3) & 1) << 3;

    auto stageKV = [&](int ks, int p) {
        #pragma unroll
        for (int ps = 0; ps < 2; ps++) {
            int s = tid + ps * 256;
            int row = s >> 3;                 // 0..63
            int ch = (s & 7) * 8;
            const __half* base = qkv + ((size_t)b * SEQ + (size_t)ks * 64 + row) * QKVDIM
                               + h * HDIM + ch;
            uint32_t doff = (uint32_t)(p * KTILE + row * APT + ch) * 2;
            cpa16(uK + doff, base + EMB, 16);
            cpa16(uV + doff, base + 2 * EMB, 16);
        }
        CP_COMMIT();
    };

    #pragma unroll 1
    for (int qi = 0; qi < 2; qi++) {
        const int T = qi == 0 ? (int)blockIdx.x : NT2 - 1 - (int)blockIdx.x;
        const int kvmax = 2 * T + 1;          // KV tiles 0..kvmax (64 rows each)

        // ---- stage Q tile (128 rows) ----
        __syncthreads();   // previous phase's smem reads complete
        #pragma unroll
        for (int ps = 0; ps < 4; ps++) {
            int s = tid + ps * 256;
            int row = s >> 3;                 // 0..127
            int ch = (s & 7) * 8;
            cpa16(uQ + (uint32_t)(row * APT + ch) * 2,
                  qkv + ((size_t)b * SEQ + (size_t)T * 128 + row) * QKVDIM + h * HDIM + ch, 16);
        }
        CP_COMMIT();
        stageKV(0, 0);
        CP_WAIT0();
        __syncthreads();

        uint32_t qf[4][4];
        #pragma unroll
        for (int kt = 0; kt < 4; kt++) {
            uint32_t ao = (uint32_t)((wid * 16 + a_row) * APT + kt * 16 + a_k) * 2;
            ldmx4(qf[kt][0], qf[kt][1], qf[kt][2], qf[kt][3], uQ + ao);
        }

        float o[8][4];
        #pragma unroll
        for (int nt = 0; nt < 8; nt++)
            #pragma unroll
            for (int r = 0; r < 4; r++) o[nt][r] = 0.f;
        float m0 = -1e30f, m1 = -1e30f, l0 = 0.f, l1 = 0.f;

        const int row_g0 = T * 128 + wid * 16 + grp;
        const int row_g1 = row_g0 + 8;

        for (int ks = 0; ks <= kvmax; ks++) {
            const int p = ks & 1;
            if (ks > 0) { CP_WAIT0(); __syncthreads(); }
            if (ks + 1 <= kvmax) stageKV(ks + 1, 1 - p);

            const uint32_t bufK = uK + (uint32_t)(p * KTILE) * 2;
            const uint32_t bufV = uV + (uint32_t)(p * KTILE) * 2;

            float s[8][4];
            #pragma unroll
            for (int nt = 0; nt < 8; nt++)
                #pragma unroll
                for (int r = 0; r < 4; r++) s[nt][r] = 0.f;
            #pragma unroll
            for (int kt = 0; kt < 4; kt++) {
                #pragma unroll
                for (int ntp = 0; ntp < 4; ntp++) {
                    uint32_t kb[2][2];
                    uint32_t bo = (uint32_t)((ntp * 16 + b_row) * APT + kt * 16 + b_k) * 2;
                    ldmx4(kb[0][0], kb[0][1], kb[1][0], kb[1][1], bufK + bo);
                    mma_f16(s[2 * ntp + 0], qf[kt], kb[0]);
                    mma_f16(s[2 * ntp + 1], qf[kt], kb[1]);
                }
            }

            const bool diag = (ks >= 2 * T);   // tiles that can cross the causal edge
            #pragma unroll
            for (int nt = 0; nt < 8; nt++) {
                int c = ks * 64 + nt * 8 + 2 * tig;
                #pragma unroll
                for (int r = 0; r < 4; r++) s[nt][r] *= scale;
                if (diag) {
                    if (c > row_g0)     s[nt][0] = -1e30f;
                    if (c + 1 > row_g0) s[nt][1] = -1e30f;
                    if (c > row_g1)     s[nt][2] = -1e30f;
                    if (c + 1 > row_g1) s[nt][3] = -1e30f;
                }
            }

            float t0 = -1e30f, t1 = -1e30f;
            #pragma unroll
            for (int nt = 0; nt < 8; nt++) {
                t0 = fmaxf(t0, fmaxf(s[nt][0], s[nt][1]));
                t1 = fmaxf(t1, fmaxf(s[nt][2], s[nt][3]));
            }
            #pragma unroll
            for (int off = 1; off < 4; off <<= 1) {
                t0 = fmaxf(t0, __shfl_xor_sync(0xffffffffu, t0, off));
                t1 = fmaxf(t1, __shfl_xor_sync(0xffffffffu, t1, off));
            }
            float nm0 = fmaxf(m0, t0), nm1 = fmaxf(m1, t1);
            float cr0 = __expf(m0 - nm0), cr1 = __expf(m1 - nm1);
            m0 = nm0; m1 = nm1;
            float rs0 = 0.f, rs1 = 0.f;
            uint32_t p01[8], p23[8];
            #pragma unroll
            for (int nt = 0; nt < 8; nt++) {
                float e0 = __expf(s[nt][0] - nm0);
                float e1 = __expf(s[nt][1] - nm0);
                float e2 = __expf(s[nt][2] - nm1);
                float e3 = __expf(s[nt][3] - nm1);
                rs0 += e0 + e1; rs1 += e2 + e3;
                p01[nt] = pack_f16(e0, e1);
                p23[nt] = pack_f16(e2, e3);
            }
            #pragma unroll
            for (int off = 1; off < 4; off <<= 1) {
                rs0 += __shfl_xor_sync(0xffffffffu, rs0, off);
                rs1 += __shfl_xor_sync(0xffffffffu, rs1, off);
            }
            l0 = l0 * cr0 + rs0;
            l1 = l1 * cr1 + rs1;
            #pragma unroll
            for (int nt = 0; nt < 8; nt++) {
                o[nt][0] *= cr0; o[nt][1] *= cr0;
                o[nt][2] *= cr1; o[nt][3] *= cr1;
            }

            #pragma unroll
            for (int kt = 0; kt < 4; kt++) {
                uint32_t a[4] = { p01[2 * kt], p23[2 * kt], p01[2 * kt + 1], p23[2 * kt + 1] };
                #pragma unroll
                for (int ntp = 0; ntp < 4; ntp++) {
                    uint32_t vb[2][2];
                    uint32_t vo = (uint32_t)((kt * 16 + a_row) * APT + ntp * 16 + a_k) * 2;
                    ldmx4t(vb[0][0], vb[0][1], vb[1][0], vb[1][1], bufV + vo);
                    mma_f16(o[2 * ntp + 0], a, vb[0]);
                    mma_f16(o[2 * ntp + 1], a, vb[1]);
                }
            }
        }

        float inv0 = 1.f / l0, inv1 = 1.f / l1;
        __half* y0 = y + ((size_t)b * SEQ + (size_t)T * 128 + wid * 16 + grp) * EMB + h * HDIM;
        __half* y1 = y0 + 8 * EMB;
        #pragma unroll
        for (int nt = 0; nt < 8; nt++) {
            int c = nt * 8 + 2 * tig;
            *(uint32_t*)(y0 + c) = pack_f16(o[nt][0] * inv0, o[nt][1] * inv0);
            *(uint32_t*)(y1 + c) = pack_f16(o[nt][2] * inv1, o[nt][3] * inv1);
        }
    }
}

// -------------------------------------------------------------------- launch
extern "C" void kernel_launch(void* const* d_in, const int* in_sizes, int n_in,
                              void* d_out, int out_size) {
    const int*   tokens = (const int*)  d_in[0];
    const float* wte    = (const float*)d_in[1];
    const float* wpe    = (const float*)d_in[2];
    const float* ln1w   = (const float*)d_in[3];
    const float* ln1b   = (const float*)d_in[4];
    const float* qkvw   = (const float*)d_in[5];
    const float* qkvb   = (const float*)d_in[6];
    const float* atpw   = (const float*)d_in[7];
    const float* atpb   = (const float*)d_in[8];
    const float* ln2w   = (const float*)d_in[9];
    const float* ln2b   = (const float*)d_in[10];
    const float* fcw    = (const float*)d_in[11];
    const float* fcb    = (const float*)d_in[12];
    const float* fpw    = (const float*)d_in[13];
    const float* fpb    = (const float*)d_in[14];
    const float* lnfw   = (const float*)d_in[15];
    const float* lnfb   = (const float*)d_in[16];
    const float* lmw    = (const float*)d_in[17];
    float* out = (float*)d_out;

    float* px;
    __half *pah, *pqkvh, *pyh, *pmh;
    __half *qh, *ah, *fh, *fl, *ph, *lh;
    cudaGetSymbolAddress((void**)&px,    g_x);
    cudaGetSymbolAddress((void**)&pah,   g_ah);
    cudaGetSymbolAddress((void**)&pqkvh, g_qkvh);
    cudaGetSymbolAddress((void**)&pyh,   g_yh);
    cudaGetSymbolAddress((void**)&pmh,   g_mh);
    cudaGetSymbolAddress((void**)&qh, g_qkvH);
    cudaGetSymbolAddress((void**)&ah, g_atpH);
    cudaGetSymbolAddress((void**)&fh, g_fcH);  cudaGetSymbolAddress((void**)&fl, g_fcL);
    cudaGetSymbolAddress((void**)&ph, g_fpH);
    cudaGetSymbolAddress((void**)&lh, g_lmH);

    const int smem128s2 = (2 * 128 * BP + 4 * 128 * BP) * 2;  // 110592 (fc, split)
    const int smem96s1  = (2 * 128 * BP + 2 * 96 * BP) * 2;   // 64512  (proj/fp)
    const int smem128s1 = (2 * 128 * BP + 2 * 128 * BP) * 2;  // 73728  (qkv, lm)
    cudaFuncSetAttribute((gemm_f16<0, 128, false>), cudaFuncAttributeMaxDynamicSharedMemorySize, smem128s1);
    cudaFuncSetAttribute((gemm_f16<2, 128, true>),  cudaFuncAttributeMaxDynamicSharedMemorySize, smem128s2);
    cudaFuncSetAttribute((gemm_f16<1, 96, false>),  cudaFuncAttributeMaxDynamicSharedMemorySize, smem96s1);
    cudaFuncSetAttribute((gemm_f16<4, 128, false>), cudaFuncAttributeMaxDynamicSharedMemorySize, smem128s1);

    const int asmem = (QTILE + 4 * KTILE) * sizeof(__half);  // 55296
    cudaFuncSetAttribute(attn_mma, cudaFuncAttributeMaxDynamicSharedMemorySize, asmem);

    dim3 tb(32, 8);
    transpose_cvt_kernel<<<dim3(QKVDIM / 32, EMB / 32, NLAYER), tb>>>(qkvw, qh, EMB, QKVDIM);
    transpose_cvt_kernel<<<dim3(EMB / 32,    EMB / 32, NLAYER), tb>>>(atpw, ah, EMB, EMB);
    transpose_split_kernel<<<dim3(FFDIM / 32,  EMB / 32, NLAYER), tb>>>(fcw,  fh, fl, EMB, FFDIM);
    transpose_cvt_kernel<<<dim3(EMB / 32,  FFDIM / 32, NLAYER), tb>>>(fpw,  ph, FFDIM, EMB);
    cvt_kernel<<<(VOCAB * EMB + 255) / 256, 256>>>(lmw, lh, VOCAB * EMB);

    embed_kernel<<<(TOKENS * EMB + 255) / 256, 256>>>(tokens, wte, wpe, px);

    for (int i = 0; i < NLAYER; i++) {
        ln_kernel<<<TOKENS / 8, 256>>>(px, ln1w + i * EMB, ln1b + i * EMB, pah);

        gemm_f16<0, 128, false><<<dim3(QKVDIM / 128, TOKENS / 128), 256, smem128s1>>>(
            pah, qh + (size_t)i * QKVDIM * EMB, nullptr,
            qkvb + i * QKVDIM, nullptr, pqkvh, TOKENS, QKVDIM, EMB);

        attn_mma<<<dim3(SEQ / 256, NHEAD, NBATCH), 256, asmem>>>(pqkvh, pyh);

        gemm_f16<1, 96, false><<<dim3(EMB / 96, TOKENS / 128), 256, smem96s1>>>(
            pyh, ah + (size_t)i * EMB * EMB, nullptr,
            atpb + i * EMB, px, px, TOKENS, EMB, EMB);

        ln_kernel<<<TOKENS / 8, 256>>>(px, ln2w + i * EMB, ln2b + i * EMB, pah);

        gemm_f16<2, 128, true><<<dim3(FFDIM / 128, TOKENS / 128), 256, smem128s2>>>(
            pah, fh + (size_t)i * FFDIM * EMB, fl + (size_t)i * FFDIM * EMB,
            fcb + i * FFDIM, nullptr, pmh, TOKENS, FFDIM, EMB);

        gemm_f16<1, 96, false><<<dim3(EMB / 96, TOKENS / 128), 256, smem96s1>>>(
            pmh, ph + (size_t)i * EMB * FFDIM, nullptr,
            fpb + i * EMB, px, px, TOKENS, EMB, FFDIM);
    }

    ln_kernel<<<TOKENS / 8, 256>>>(px, lnfw, lnfb, pah);

    gemm_f16<4, 128, false><<<dim3(TOKENS / 128, (VOCAB + 127) / 128), 256, smem128s1>>>(
        pah, lh, nullptr, nullptr, nullptr, out, TOKENS, VOCAB, EMB);
}